// round 16
// baseline (speedup 1.0000x reference)
#include <cuda_runtime.h>
#include <cuda_bf16.h>
#include <cuda_fp16.h>
#include <cstdint>

#define DIN 128
#define DH  256
#define G_MAX 20000
#define NTILES_MAX 3907          // ceil(500000/128)

// ---------------------------------------------------------------------------
// Persistent scratch
// ---------------------------------------------------------------------------
__device__ float d_pooled[G_MAX * DH];
// W1^T (fp16), smem-image [n=256][k pad 136]
__device__ __align__(16) __half d_W1h[256 * 136];
// W2^T (fp16) in 2 N-halves: [half][n_local=128][k=256 pad 264]
__device__ __align__(16) __half d_W2hB[2][128 * 264];
// Wg1^T (fp16) in 2 K-chunks of 128: [chunk][n=256][kk pad 136]
__device__ __align__(16) __half d_Wg1h[2][256 * 136];
// x1 inter-layer scratch: [tile][128 rows][264 pad] fp16 = 67584 B/tile
__device__ __align__(16) __half d_x1[(size_t)NTILES_MAX * 33792];

// ---------------------------------------------------------------------------
// helpers
// ---------------------------------------------------------------------------
__device__ __forceinline__ uint32_t smem_to_u32(const void* p) {
    uint32_t a;
    asm("{ .reg .u64 t; cvta.to.shared.u64 t, %1; cvt.u32.u64 %0, t; }" : "=r"(a) : "l"(p));
    return a;
}
__device__ __forceinline__ void sts32(uint32_t a, uint32_t v) {
    asm volatile("st.shared.b32 [%0], %1;" :: "r"(a), "r"(v));
}
__device__ __forceinline__ void cp16(uint32_t s, const void* g) {
    asm volatile("cp.async.ca.shared.global [%0], [%1], 16;" :: "r"(s), "l"(g));
}
#define CP_COMMIT() asm volatile("cp.async.commit_group;" ::: "memory")
#define CP_WAITN(n) asm volatile("cp.async.wait_group %0;" :: "n"(n) : "memory")

__device__ __forceinline__ void ldsm4(uint32_t& r0, uint32_t& r1, uint32_t& r2, uint32_t& r3,
                                      uint32_t addr) {
    asm volatile("ldmatrix.sync.aligned.m8n8.x4.shared.b16 {%0,%1,%2,%3}, [%4];"
                 : "=r"(r0), "=r"(r1), "=r"(r2), "=r"(r3) : "r"(addr));
}
__device__ __forceinline__ void mma_f16(float* d, uint32_t a0, uint32_t a1, uint32_t a2,
                                        uint32_t a3, uint32_t b0, uint32_t b1) {
    asm volatile(
        "mma.sync.aligned.m16n8k16.row.col.f32.f16.f16.f32 "
        "{%0,%1,%2,%3}, {%4,%5,%6,%7}, {%8,%9}, {%0,%1,%2,%3};"
        : "+f"(d[0]), "+f"(d[1]), "+f"(d[2]), "+f"(d[3])
        : "r"(a0), "r"(a1), "r"(a2), "r"(a3), "r"(b0), "r"(b1));
}
__device__ __forceinline__ uint32_t pack2h(float v0, float v1) {
    __half h0 = __float2half(v0), h1 = __float2half(v1);
    return (uint32_t)__half_as_ushort(h0) | ((uint32_t)__half_as_ushort(h1) << 16);
}

// ---------------------------------------------------------------------------
// Kernel 0: zero pooled accumulator
// ---------------------------------------------------------------------------
__global__ void zero_pooled_kernel(int total) {
    int i = blockIdx.x * blockDim.x + threadIdx.x;
    int stride = gridDim.x * blockDim.x;
    for (; i < total; i += stride) d_pooled[i] = 0.0f;
}

// ---------------------------------------------------------------------------
// Kernel P: bake W1^T / W2^T / Wg1^T into fp16 images
// ---------------------------------------------------------------------------
__global__ void prep_kernel(const float* __restrict__ W1, const float* __restrict__ W2,
                            const float* __restrict__ Wg1) {
    int idx = blockIdx.x * blockDim.x + threadIdx.x;
    if (idx < DIN * DH) {                          // W1 [k=128][n=256]
        int k = idx / DH, n = idx % DH;
        d_W1h[n * 136 + k] = __float2half(W1[idx]);
    } else if (idx < DIN * DH + DH * DH) {         // W2 [k=256][n=256]
        int i2 = idx - DIN * DH;
        int k = i2 / DH, n = i2 % DH;
        d_W2hB[n >> 7][(n & 127) * 264 + k] = __float2half(W2[i2]);
    } else if (idx < DIN * DH + 2 * DH * DH) {     // Wg1 [k=256][n=256]
        int i2 = idx - DIN * DH - DH * DH;
        int k = i2 / DH, n = i2 % DH;
        d_Wg1h[k >> 7][n * 136 + (k & 127)] = __float2half(Wg1[i2]);
    }
}

// ---------------------------------------------------------------------------
// Kernel A: layer 1, persistent, W1 resident. 148 CTAs x 512 threads.
// Warp grid 4M x 4N (32x64 per-warp tile), 128-row tiles.
// smem: W1 @0 (69632), STAGE @69632 (67584: A1 [128][136] region then x1 [128][264]),
//       HBUF @137216 (65536 fp32 h tile), b1s @202752 -> 203776 B
// ---------------------------------------------------------------------------
#define KA_W1   0
#define KA_STG  69632
#define KA_HBUF 137216
#define KA_B1S  202752
#define KA_SMEM 203776

extern "C" __global__ void __launch_bounds__(512, 1)
layer1_kernel(const float* __restrict__ h, const float* __restrict__ b1,
              int n_atoms, int ntiles)
{
    extern __shared__ unsigned char sm[];
    const uint32_t smb = smem_to_u32(sm);
    const int tid = threadIdx.x;
    const int w   = tid >> 5;
    const int l   = tid & 31;
    const int q   = l >> 2;
    const int m   = l & 3;
    const int wm  = w >> 2;            // 0..3
    const int wn  = w & 3;             // 0..3
    const int Rb  = wm * 32;
    const int Cb  = wn * 64;

    const int aRow  = l & 15;
    const int aKoff = (l >> 4) * 8;
    const int bN    = (l >> 4) * 8 + (l & 7);
    const int bKoff = ((l >> 3) & 1) * 8;

    float* b1s = (float*)(sm + KA_B1S);

    // ---- prologue: W1 image (resident for whole kernel) ----
    {
        const char* p = (const char*)&d_W1h[0];
        for (int i = tid; i < 4352; i += 512) cp16(smb + KA_W1 + i * 16, p + i * 16);
        CP_COMMIT();
    }
    if (tid < 256) b1s[tid] = b1[tid];

    int t = blockIdx.x;
    // ---- first h tile ----
    if (t < ntiles) {
        int rows = n_atoms - t * 128; if (rows > 128) rows = 128;
        int nv = rows * 32;                       // valid float4 count
        const char* src = (const char*)(h + (size_t)t * 128 * DIN);
        for (int i = tid; i < 4096; i += 512) {
            if (i < nv) cp16(smb + KA_HBUF + i * 16, src + i * 16);
            else *(float4*)(sm + KA_HBUF + i * 16) = make_float4(0.f, 0.f, 0.f, 0.f);
        }
    }
    CP_COMMIT();

    const uint32_t aBase = smb + KA_STG + (uint32_t)(((Rb + aRow) * 136 + aKoff) * 2);
    const uint32_t bBase = smb + KA_W1 + (uint32_t)(((Cb + bN) * 136 + bKoff) * 2);

    while (t < ntiles) {
        CP_WAITN(0);
        __syncthreads();

        // ---- convert h fp32 -> A1 fp16 [r][136] ----
        #pragma unroll
        for (int it = 0; it < 8; it++) {
            int idx = tid + it * 512;             // 128 rows x 32 f4
            int r = idx >> 5, c4 = idx & 31;
            float4 v = *(const float4*)(sm + KA_HBUF + idx * 16);
            uint32_t off = (uint32_t)(r * 136 + c4 * 4) * 2;
            *(uint2*)(sm + KA_STG + off) = make_uint2(pack2h(v.x, v.y), pack2h(v.z, v.w));
        }
        __syncthreads();

        // ---- prefetch next h tile (overlaps MMA + epilogue + copy) ----
        int tn = t + 148;
        if (tn < ntiles) {
            int rows = n_atoms - tn * 128; if (rows > 128) rows = 128;
            int nv = rows * 32;
            const char* src = (const char*)(h + (size_t)tn * 128 * DIN);
            for (int i = tid; i < 4096; i += 512) {
                if (i < nv) cp16(smb + KA_HBUF + i * 16, src + i * 16);
                else *(float4*)(sm + KA_HBUF + i * 16) = make_float4(0.f, 0.f, 0.f, 0.f);
            }
        }
        CP_COMMIT();

        // ---- layer-1 MMA: K=128, 8 k-steps ----
        float acc[64];
        #pragma unroll
        for (int i = 0; i < 64; i++) acc[i] = 0.f;
        #pragma unroll
        for (int ks = 0; ks < 8; ks++) {
            uint32_t aH[8];
            ldsm4(aH[0], aH[1], aH[2], aH[3], aBase + ks * 32);
            ldsm4(aH[4], aH[5], aH[6], aH[7], aBase + 16 * 272 + ks * 32);
            #pragma unroll
            for (int nfp = 0; nfp < 4; nfp++) {
                uint32_t b0a, b1a, b0b, b1b;
                ldsm4(b0a, b1a, b0b, b1b, bBase + nfp * 16 * 272 + ks * 32);
                #pragma unroll
                for (int mf = 0; mf < 2; mf++) {
                    mma_f16(acc + (mf * 8 + nfp * 2) * 4,
                            aH[mf*4], aH[mf*4+1], aH[mf*4+2], aH[mf*4+3], b0a, b1a);
                    mma_f16(acc + (mf * 8 + nfp * 2 + 1) * 4,
                            aH[mf*4], aH[mf*4+1], aH[mf*4+2], aH[mf*4+3], b0b, b1b);
                }
            }
        }
        __syncthreads();   // all MMA reads of STAGE(A1) done

        // ---- epilogue: bias+relu, fp16 -> stage [r][264] ----
        #pragma unroll
        for (int mf = 0; mf < 2; mf++) {
            #pragma unroll
            for (int nf = 0; nf < 8; nf++) {
                int idx = (mf * 8 + nf) * 4;
                int c = Cb + nf * 8 + m * 2;
                int R = Rb + mf * 16 + q;
                float v0 = fmaxf(acc[idx+0] + b1s[c],     0.f);
                float v1 = fmaxf(acc[idx+1] + b1s[c + 1], 0.f);
                float v2 = fmaxf(acc[idx+2] + b1s[c],     0.f);
                float v3 = fmaxf(acc[idx+3] + b1s[c + 1], 0.f);
                uint32_t off = (uint32_t)((R * 264 + c) * 2);
                sts32(smb + KA_STG + off, pack2h(v0, v1));
                sts32(smb + KA_STG + off + 4224, pack2h(v2, v3));   // row +8
            }
        }
        __syncthreads();

        // ---- coalesced copy stage -> d_x1 blob ----
        {
            const float4* ss = (const float4*)(sm + KA_STG);
            float4* dd = (float4*)(d_x1 + (size_t)t * 33792);
            for (int i = tid; i < 4224; i += 512) dd[i] = ss[i];
        }
        t = tn;
    }
}

// ---------------------------------------------------------------------------
// Kernel B: layer 2 + pool, persistent, W2 N-half resident. 296 CTAs x 256
// threads, 2 CTAs/SM. Each CTA: colhalf fixed, loops (tile,rowhalf) quadrants.
// Warp grid 2M x 4N (32x32 per-warp tile) over 64 rows x 128 cols.
// smem: W2half @0 (67584), A/X2 @67584 (33792), b2s @101376, gids @101888
//       -> 102144 B  (2 CTAs/SM)
// ---------------------------------------------------------------------------
#define KB_W2  0
#define KB_A   67584
#define KB_B2S 101376
#define KB_GID 101888
#define KB_SMEM 102144

extern "C" __global__ void __launch_bounds__(256, 2)
layer2_kernel(const int* __restrict__ graph_ids, const float* __restrict__ b2,
              int n_atoms, int ntiles)
{
    extern __shared__ unsigned char sm[];
    const uint32_t smb = smem_to_u32(sm);
    const int tid = threadIdx.x;
    const int w   = tid >> 5;
    const int l   = tid & 31;
    const int q   = l >> 2;
    const int m   = l & 3;
    const int wm  = w >> 2;            // 0..1  (32 rows)
    const int wn  = w & 3;             // 0..3  (32 cols)
    const int Rb  = wm * 32;
    const int Cbl = wn * 32;
    const int colhalf = blockIdx.x & 1;

    const int aRow  = l & 15;
    const int aKoff = (l >> 4) * 8;
    const int bN    = (l >> 4) * 8 + (l & 7);
    const int bKoff = ((l >> 3) & 1) * 8;

    float* b2s = (float*)(sm + KB_B2S);
    int*   gids = (int*)(sm + KB_GID);

    // ---- prologue: W2 half image (resident) ----
    {
        const char* p = (const char*)&d_W2hB[colhalf][0];
        for (int i = tid; i < 4224; i += 256) cp16(smb + KB_W2 + i * 16, p + i * 16);
        CP_COMMIT();
    }
    if (tid < 128) b2s[tid] = b2[colhalf * 128 + tid];

    const uint32_t aBase = smb + KB_A + (uint32_t)(((Rb + aRow) * 264 + aKoff) * 2);
    const uint32_t bBase = smb + KB_W2 + (uint32_t)(((Cbl + bN) * 264 + bKoff) * 2);
    const int nq = 2 * ntiles;

    for (int qid = blockIdx.x >> 1; qid < nq; qid += 148) {
        const int tile = qid >> 1;
        const int rh   = qid & 1;

        // gids for this quadrant's 64 rows
        if (tid < 64) {
            int grow = tile * 128 + rh * 64 + tid;
            gids[tid] = (grow < n_atoms) ? graph_ids[grow] : -1;
        }
        // load x1 quadrant rows (contiguous 33792 B)
        {
            const char* src = (const char*)(d_x1 + (size_t)tile * 33792 + rh * 16896);
            for (int i = tid; i < 2112; i += 256) cp16(smb + KB_A + i * 16, src + i * 16);
            CP_COMMIT();
        }
        CP_WAITN(0);
        __syncthreads();

        // ---- GEMM: 64 x 128, K=256 ----
        float acc[32];
        #pragma unroll
        for (int i = 0; i < 32; i++) acc[i] = 0.f;
        #pragma unroll
        for (int ks = 0; ks < 16; ks++) {
            uint32_t aH[8];
            ldsm4(aH[0], aH[1], aH[2], aH[3], aBase + ks * 32);
            ldsm4(aH[4], aH[5], aH[6], aH[7], aBase + 16 * 528 + ks * 32);
            #pragma unroll
            for (int nfp = 0; nfp < 2; nfp++) {
                uint32_t b0a, b1a, b0b, b1b;
                ldsm4(b0a, b1a, b0b, b1b, bBase + nfp * 16 * 528 + ks * 32);
                #pragma unroll
                for (int mf = 0; mf < 2; mf++) {
                    mma_f16(acc + (mf * 4 + nfp * 2) * 4,
                            aH[mf*4], aH[mf*4+1], aH[mf*4+2], aH[mf*4+3], b0a, b1a);
                    mma_f16(acc + (mf * 4 + nfp * 2 + 1) * 4,
                            aH[mf*4], aH[mf*4+1], aH[mf*4+2], aH[mf*4+3], b0b, b1b);
                }
            }
        }
        __syncthreads();   // all reads of KB_A done; X2 may alias

        // ---- X2 = relu(acc + b2) into KB_A as fp32 [64][132] ----
        {
            float* X2 = (float*)(sm + KB_A);
            #pragma unroll
            for (int mf = 0; mf < 2; mf++) {
                #pragma unroll
                for (int nf = 0; nf < 4; nf++) {
                    int idx = (mf * 4 + nf) * 4;
                    int cl = Cbl + nf * 8 + m * 2;
                    int R  = Rb + mf * 16 + q;
                    X2[R * 132 + cl]           = fmaxf(acc[idx+0] + b2s[cl],     0.f);
                    X2[R * 132 + cl + 1]       = fmaxf(acc[idx+1] + b2s[cl + 1], 0.f);
                    X2[(R + 8) * 132 + cl]     = fmaxf(acc[idx+2] + b2s[cl],     0.f);
                    X2[(R + 8) * 132 + cl + 1] = fmaxf(acc[idx+3] + b2s[cl + 1], 0.f);
                }
            }
        }
        __syncthreads();

        // ---- segmented pool over sorted gids, then atomics ----
        {
            const int col = tid & 127;
            const int rlo = (tid >> 7) * 32;
            const float* X2 = (const float*)(sm + KB_A);
            int cur = -1;
            float s = 0.f;
            #pragma unroll 8
            for (int rr = 0; rr < 32; rr++) {
                int r = rlo + rr;
                int g = gids[r];
                if (g != cur) {
                    if (cur >= 0) atomicAdd(&d_pooled[(size_t)cur * DH + colhalf * 128 + col], s);
                    cur = g;
                    s = 0.f;
                }
                if (g >= 0) s += X2[r * 132 + col];
            }
            if (cur >= 0) atomicAdd(&d_pooled[(size_t)cur * DH + colhalf * 128 + col], s);
        }
        __syncthreads();   // pool reads done before next x1 overwrite
    }
}

// ---------------------------------------------------------------------------
// Kernel 2: graph MLP, fp16 mma + ldmatrix, 64-graph tile (unchanged, ~25us)
// ---------------------------------------------------------------------------
#define GA     0
#define GW     33792
#define GWSTR  69632
#define GSO_BG1 173056
#define GSO_WS  174080
#define GSO_RS  175104
#define GRAPH_SMEM_BYTES 176128
#define TILE 64

extern "C" __global__ void __launch_bounds__(256, 1)
graph_kernel(const float* __restrict__ bg1, const float* __restrict__ Wg2,
             const float* __restrict__ bg2, float* __restrict__ out, int num_graphs)
{
    extern __shared__ unsigned char sm[];
    const uint32_t smb = smem_to_u32(sm);
    const int tid = threadIdx.x;
    const int l   = tid & 31;
    const int q   = l >> 2;
    const int m   = l & 3;
    const int w   = tid >> 5;
    const int wm  = w >> 2;
    const int wn  = w & 3;
    const int Rb  = wm * 32;
    const int Cb  = wn * 64;
    const int g0  = blockIdx.x * TILE;

    const int aRow  = l & 15;
    const int aKoff = (l >> 4) * 8;
    const int bN    = (l >> 4) * 8 + (l & 7);
    const int bKoff = ((l >> 3) & 1) * 8;

    float* bg1s = (float*)(sm + GSO_BG1);
    float* wsv  = (float*)(sm + GSO_WS);
    float* rs   = (float*)(sm + GSO_RS);

    #pragma unroll
    for (int cc = 0; cc < 2; cc++) {
        const char* p = (const char*)&d_Wg1h[cc][0];
        uint32_t dst = smb + GW + cc * GWSTR;
        #pragma unroll
        for (int it = 0; it < 17; it++) {
            int o = (tid + it * 256) * 16;
            cp16(dst + o, p + o);
        }
        CP_COMMIT();
    }

    bg1s[tid] = bg1[tid];
    wsv[tid]  = Wg2[tid];

    #pragma unroll 4
    for (int it = 0; it < 16; it++) {
        int idx = tid + it * 256;
        int r = idx >> 6, c = (idx & 63) * 4;
        float4 v = make_float4(0.f, 0.f, 0.f, 0.f);
        if (g0 + r < num_graphs)
            v = *(const float4*)(d_pooled + (size_t)(g0 + r) * DH + c);
        uint32_t off = (uint32_t)(r * 264 + c) * 2;
        *(uint2*)(sm + GA + off) = make_uint2(pack2h(v.x, v.y), pack2h(v.z, v.w));
    }

    float acc[64];
    #pragma unroll
    for (int i = 0; i < 64; i++) acc[i] = 0.f;

    {
        const uint32_t aBase = smb + GA + (uint32_t)(((Rb + aRow) * 264 + aKoff) * 2);
        #pragma unroll
        for (int half = 0; half < 2; half++) {
            if (half == 0) CP_WAITN(1); else CP_WAITN(0);
            __syncthreads();
            const uint32_t bBase = smb + GW + half * GWSTR
                                 + (uint32_t)(((Cb + bN) * 136 + bKoff) * 2);
            #pragma unroll
            for (int kk = 0; kk < 8; kk++) {
                uint32_t aH[8];
                ldsm4(aH[0], aH[1], aH[2], aH[3], aBase + half * 256 + kk * 32);
                ldsm4(aH[4], aH[5], aH[6], aH[7], aBase + 16 * 528 + half * 256 + kk * 32);
                #pragma unroll
                for (int nfp = 0; nfp < 4; nfp++) {
                    uint32_t b0a, b1a, b0b, b1b;
                    ldsm4(b0a, b1a, b0b, b1b, bBase + nfp * 16 * 272 + kk * 32);
                    #pragma unroll
                    for (int mf = 0; mf < 2; mf++) {
                        mma_f16(acc + (mf * 8 + nfp * 2) * 4,
                                aH[mf*4], aH[mf*4+1], aH[mf*4+2], aH[mf*4+3], b0a, b1a);
                        mma_f16(acc + (mf * 8 + nfp * 2 + 1) * 4,
                                aH[mf*4], aH[mf*4+1], aH[mf*4+2], aH[mf*4+3], b0b, b1b);
                    }
                }
            }
        }
    }

    #pragma unroll
    for (int mf = 0; mf < 2; mf++) {
        float p0 = 0.f, p1 = 0.f;
        #pragma unroll
        for (int nf = 0; nf < 8; nf++) {
            int idx = (mf * 8 + nf) * 4;
            int c = Cb + nf * 8 + m * 2;
            float w0 = wsv[c], w1 = wsv[c + 1];
            p0 += fmaxf(acc[idx+0] + bg1s[c],     0.f) * w0
                + fmaxf(acc[idx+1] + bg1s[c + 1], 0.f) * w1;
            p1 += fmaxf(acc[idx+2] + bg1s[c],     0.f) * w0
                + fmaxf(acc[idx+3] + bg1s[c + 1], 0.f) * w1;
        }
        p0 += __shfl_xor_sync(0xffffffffu, p0, 1);
        p0 += __shfl_xor_sync(0xffffffffu, p0, 2);
        p1 += __shfl_xor_sync(0xffffffffu, p1, 1);
        p1 += __shfl_xor_sync(0xffffffffu, p1, 2);
        if (m == 0) {
            int R = Rb + mf * 16 + q;
            rs[R * 4 + wn]       = p0;
            rs[(R + 8) * 4 + wn] = p1;
        }
    }
    __syncthreads();
    if (tid < TILE) {
        int g = g0 + tid;
        if (g < num_graphs)
            out[g] = rs[tid * 4] + rs[tid * 4 + 1] + rs[tid * 4 + 2] + rs[tid * 4 + 3] + bg2[0];
    }
}

// ---------------------------------------------------------------------------
extern "C" void kernel_launch(void* const* d_in, const int* in_sizes, int n_in,
                              void* d_out, int out_size) {
    const float* h         = (const float*)d_in[0];
    const int*   graph_ids = (const int*)  d_in[1];
    const int base = (n_in >= 11) ? 3 : 2;   // skip num_graphs scalar slot if present
    const float* W1  = (const float*)d_in[base + 0];
    const float* b1  = (const float*)d_in[base + 1];
    const float* W2  = (const float*)d_in[base + 2];
    const float* b2  = (const float*)d_in[base + 3];
    const float* Wg1 = (const float*)d_in[base + 4];
    const float* bg1 = (const float*)d_in[base + 5];
    const float* Wg2 = (const float*)d_in[base + 6];
    const float* bg2 = (const float*)d_in[base + 7];
    float* out = (float*)d_out;

    const int n_atoms = in_sizes[0] / DIN;
    int ntiles = (n_atoms + 127) / 128;
    if (ntiles > NTILES_MAX) ntiles = NTILES_MAX;
    const int G = out_size;                  // D_OUT = 1

    static bool attrs_set = false;
    if (!attrs_set) {
        cudaFuncSetAttribute(layer1_kernel,
                             cudaFuncAttributeMaxDynamicSharedMemorySize, KA_SMEM);
        cudaFuncSetAttribute(layer2_kernel,
                             cudaFuncAttributeMaxDynamicSharedMemorySize, KB_SMEM);
        cudaFuncSetAttribute(graph_kernel,
                             cudaFuncAttributeMaxDynamicSharedMemorySize, GRAPH_SMEM_BYTES);
        attrs_set = true;
    }

    prep_kernel<<<(DIN * DH + 2 * DH * DH + 255) / 256, 256>>>(W1, W2, Wg1);
    zero_pooled_kernel<<<512, 256>>>(G * DH);

    layer1_kernel<<<148, 512, KA_SMEM>>>(h, b1, n_atoms, ntiles);
    layer2_kernel<<<296, 256, KB_SMEM>>>(graph_ids, b2, n_atoms, ntiles);

    int gblocks = (G + TILE - 1) / TILE;
    graph_kernel<<<gblocks, 256, GRAPH_SMEM_BYTES>>>(bg1, Wg2, bg2, out, G);
}

// round 17
// speedup vs baseline: 1.0866x; 1.0866x over previous
#include <cuda_runtime.h>
#include <cuda_bf16.h>
#include <cuda_fp16.h>
#include <cstdint>

#define DIN 128
#define DH  256
#define G_MAX 20000
#define NTILES_MAX 3907          // ceil(500000/128)

// ---------------------------------------------------------------------------
// Persistent scratch
// ---------------------------------------------------------------------------
__device__ float d_pooled[G_MAX * DH];
// W1^T (fp16), smem-image [n=256][k pad 136]
__device__ __align__(16) __half d_W1h[256 * 136];
// W2^T (fp16): contiguous [n=256][k=256 pad 264]
__device__ __align__(16) __half d_W2hB[256 * 264];
// Wg1^T (fp16) in 2 K-chunks of 128: [chunk][n=256][kk pad 136]
__device__ __align__(16) __half d_Wg1h[2][256 * 136];
// x1 inter-layer scratch: [tile][128 rows][264 pad] fp16 = 67584 B/tile
__device__ __align__(16) __half d_x1[(size_t)NTILES_MAX * 33792];

// ---------------------------------------------------------------------------
// helpers
// ---------------------------------------------------------------------------
__device__ __forceinline__ uint32_t smem_to_u32(const void* p) {
    uint32_t a;
    asm("{ .reg .u64 t; cvta.to.shared.u64 t, %1; cvt.u32.u64 %0, t; }" : "=r"(a) : "l"(p));
    return a;
}
__device__ __forceinline__ void sts32(uint32_t a, uint32_t v) {
    asm volatile("st.shared.b32 [%0], %1;" :: "r"(a), "r"(v));
}
__device__ __forceinline__ void cp16(uint32_t s, const void* g) {
    asm volatile("cp.async.ca.shared.global [%0], [%1], 16;" :: "r"(s), "l"(g));
}
#define CP_COMMIT() asm volatile("cp.async.commit_group;" ::: "memory")
#define CP_WAITN(n) asm volatile("cp.async.wait_group %0;" :: "n"(n) : "memory")

__device__ __forceinline__ void ldsm4(uint32_t& r0, uint32_t& r1, uint32_t& r2, uint32_t& r3,
                                      uint32_t addr) {
    asm volatile("ldmatrix.sync.aligned.m8n8.x4.shared.b16 {%0,%1,%2,%3}, [%4];"
                 : "=r"(r0), "=r"(r1), "=r"(r2), "=r"(r3) : "r"(addr));
}
__device__ __forceinline__ void mma_f16(float* d, uint32_t a0, uint32_t a1, uint32_t a2,
                                        uint32_t a3, uint32_t b0, uint32_t b1) {
    asm volatile(
        "mma.sync.aligned.m16n8k16.row.col.f32.f16.f16.f32 "
        "{%0,%1,%2,%3}, {%4,%5,%6,%7}, {%8,%9}, {%0,%1,%2,%3};"
        : "+f"(d[0]), "+f"(d[1]), "+f"(d[2]), "+f"(d[3])
        : "r"(a0), "r"(a1), "r"(a2), "r"(a3), "r"(b0), "r"(b1));
}
__device__ __forceinline__ uint32_t pack2h(float v0, float v1) {
    __half h0 = __float2half(v0), h1 = __float2half(v1);
    return (uint32_t)__half_as_ushort(h0) | ((uint32_t)__half_as_ushort(h1) << 16);
}

// ---------------------------------------------------------------------------
// Kernel 0: zero pooled accumulator
// ---------------------------------------------------------------------------
__global__ void zero_pooled_kernel(int total) {
    int i = blockIdx.x * blockDim.x + threadIdx.x;
    int stride = gridDim.x * blockDim.x;
    for (; i < total; i += stride) d_pooled[i] = 0.0f;
}

// ---------------------------------------------------------------------------
// Kernel P: bake W1^T / W2^T / Wg1^T into fp16 images
// ---------------------------------------------------------------------------
__global__ void prep_kernel(const float* __restrict__ W1, const float* __restrict__ W2,
                            const float* __restrict__ Wg1) {
    int idx = blockIdx.x * blockDim.x + threadIdx.x;
    if (idx < DIN * DH) {                          // W1 [k=128][n=256]
        int k = idx / DH, n = idx % DH;
        d_W1h[n * 136 + k] = __float2half(W1[idx]);
    } else if (idx < DIN * DH + DH * DH) {         // W2 [k=256][n=256]
        int i2 = idx - DIN * DH;
        int k = i2 / DH, n = i2 % DH;
        d_W2hB[n * 264 + k] = __float2half(W2[i2]);
    } else if (idx < DIN * DH + 2 * DH * DH) {     // Wg1 [k=256][n=256]
        int i2 = idx - DIN * DH - DH * DH;
        int k = i2 / DH, n = i2 % DH;
        d_Wg1h[k >> 7][n * 136 + (k & 127)] = __float2half(Wg1[i2]);
    }
}

// ---------------------------------------------------------------------------
// Kernel A: layer 1, persistent, W1 resident. 148 CTAs x 512 threads.
// (unchanged from R16 — measured ~185us)
// ---------------------------------------------------------------------------
#define KA_W1   0
#define KA_STG  69632
#define KA_HBUF 137216
#define KA_B1S  202752
#define KA_SMEM 203776

extern "C" __global__ void __launch_bounds__(512, 1)
layer1_kernel(const float* __restrict__ h, const float* __restrict__ b1,
              int n_atoms, int ntiles)
{
    extern __shared__ unsigned char sm[];
    const uint32_t smb = smem_to_u32(sm);
    const int tid = threadIdx.x;
    const int w   = tid >> 5;
    const int l   = tid & 31;
    const int q   = l >> 2;
    const int m   = l & 3;
    const int wm  = w >> 2;            // 0..3
    const int wn  = w & 3;             // 0..3
    const int Rb  = wm * 32;
    const int Cb  = wn * 64;

    const int aRow  = l & 15;
    const int aKoff = (l >> 4) * 8;
    const int bN    = (l >> 4) * 8 + (l & 7);
    const int bKoff = ((l >> 3) & 1) * 8;

    float* b1s = (float*)(sm + KA_B1S);

    {
        const char* p = (const char*)&d_W1h[0];
        for (int i = tid; i < 4352; i += 512) cp16(smb + KA_W1 + i * 16, p + i * 16);
        CP_COMMIT();
    }
    if (tid < 256) b1s[tid] = b1[tid];

    int t = blockIdx.x;
    if (t < ntiles) {
        int rows = n_atoms - t * 128; if (rows > 128) rows = 128;
        int nv = rows * 32;
        const char* src = (const char*)(h + (size_t)t * 128 * DIN);
        for (int i = tid; i < 4096; i += 512) {
            if (i < nv) cp16(smb + KA_HBUF + i * 16, src + i * 16);
            else *(float4*)(sm + KA_HBUF + i * 16) = make_float4(0.f, 0.f, 0.f, 0.f);
        }
    }
    CP_COMMIT();

    const uint32_t aBase = smb + KA_STG + (uint32_t)(((Rb + aRow) * 136 + aKoff) * 2);
    const uint32_t bBase = smb + KA_W1 + (uint32_t)(((Cb + bN) * 136 + bKoff) * 2);

    while (t < ntiles) {
        CP_WAITN(0);
        __syncthreads();

        #pragma unroll
        for (int it = 0; it < 8; it++) {
            int idx = tid + it * 512;
            int r = idx >> 5, c4 = idx & 31;
            float4 v = *(const float4*)(sm + KA_HBUF + idx * 16);
            uint32_t off = (uint32_t)(r * 136 + c4 * 4) * 2;
            *(uint2*)(sm + KA_STG + off) = make_uint2(pack2h(v.x, v.y), pack2h(v.z, v.w));
        }
        __syncthreads();

        int tn = t + 148;
        if (tn < ntiles) {
            int rows = n_atoms - tn * 128; if (rows > 128) rows = 128;
            int nv = rows * 32;
            const char* src = (const char*)(h + (size_t)tn * 128 * DIN);
            for (int i = tid; i < 4096; i += 512) {
                if (i < nv) cp16(smb + KA_HBUF + i * 16, src + i * 16);
                else *(float4*)(sm + KA_HBUF + i * 16) = make_float4(0.f, 0.f, 0.f, 0.f);
            }
        }
        CP_COMMIT();

        float acc[64];
        #pragma unroll
        for (int i = 0; i < 64; i++) acc[i] = 0.f;
        #pragma unroll
        for (int ks = 0; ks < 8; ks++) {
            uint32_t aH[8];
            ldsm4(aH[0], aH[1], aH[2], aH[3], aBase + ks * 32);
            ldsm4(aH[4], aH[5], aH[6], aH[7], aBase + 16 * 272 + ks * 32);
            #pragma unroll
            for (int nfp = 0; nfp < 4; nfp++) {
                uint32_t b0a, b1a, b0b, b1b;
                ldsm4(b0a, b1a, b0b, b1b, bBase + nfp * 16 * 272 + ks * 32);
                #pragma unroll
                for (int mf = 0; mf < 2; mf++) {
                    mma_f16(acc + (mf * 8 + nfp * 2) * 4,
                            aH[mf*4], aH[mf*4+1], aH[mf*4+2], aH[mf*4+3], b0a, b1a);
                    mma_f16(acc + (mf * 8 + nfp * 2 + 1) * 4,
                            aH[mf*4], aH[mf*4+1], aH[mf*4+2], aH[mf*4+3], b0b, b1b);
                }
            }
        }
        __syncthreads();

        #pragma unroll
        for (int mf = 0; mf < 2; mf++) {
            #pragma unroll
            for (int nf = 0; nf < 8; nf++) {
                int idx = (mf * 8 + nf) * 4;
                int c = Cb + nf * 8 + m * 2;
                int R = Rb + mf * 16 + q;
                float v0 = fmaxf(acc[idx+0] + b1s[c],     0.f);
                float v1 = fmaxf(acc[idx+1] + b1s[c + 1], 0.f);
                float v2 = fmaxf(acc[idx+2] + b1s[c],     0.f);
                float v3 = fmaxf(acc[idx+3] + b1s[c + 1], 0.f);
                uint32_t off = (uint32_t)((R * 264 + c) * 2);
                sts32(smb + KA_STG + off, pack2h(v0, v1));
                sts32(smb + KA_STG + off + 4224, pack2h(v2, v3));
            }
        }
        __syncthreads();

        {
            const float4* ss = (const float4*)(sm + KA_STG);
            float4* dd = (float4*)(d_x1 + (size_t)t * 33792);
            for (int i = tid; i < 4224; i += 512) dd[i] = ss[i];
        }
        t = tn;
    }
}

// ---------------------------------------------------------------------------
// Kernel B v2: layer 2 + pool. 148 persistent CTAs x 512 threads, 1 CTA/SM.
// Full W2 [256][264] resident (135 KB). Double-buffered 64-row x1 quadrants.
// Warp grid 2M x 8N (32x32 per-warp tile) over 64 rows x 256 cols.
// smem: W2 @0 (135168), BUF0 @135168 (33792), BUF1 @168960 (33792),
//       b2s @202752 (1024), gids @203776 (256) -> 204032 B
// ---------------------------------------------------------------------------
#define KB_W2  0
#define KB_B0  135168
#define KB_BSZ 33792
#define KB_B2S 202752
#define KB_GID 203776
#define KB_SMEM 204032

extern "C" __global__ void __launch_bounds__(512, 1)
layer2_kernel(const int* __restrict__ graph_ids, const float* __restrict__ b2,
              int n_atoms, int ntiles)
{
    extern __shared__ unsigned char sm[];
    const uint32_t smb = smem_to_u32(sm);
    const int tid = threadIdx.x;
    const int w   = tid >> 5;
    const int l   = tid & 31;
    const int q   = l >> 2;
    const int m   = l & 3;
    const int wm  = w >> 3;            // 0..1  (32 rows)
    const int wn  = w & 7;             // 0..7  (32 cols)
    const int Rb  = wm * 32;
    const int Cb  = wn * 32;

    const int aRow  = l & 15;
    const int aKoff = (l >> 4) * 8;
    const int bN    = (l >> 4) * 8 + (l & 7);
    const int bKoff = ((l >> 3) & 1) * 8;

    float* b2s = (float*)(sm + KB_B2S);
    int*   gids = (int*)(sm + KB_GID);

    // ---- prologue: full W2 image (resident), group 0 ----
    {
        const char* p = (const char*)&d_W2hB[0];
        for (int i = tid; i < 8448; i += 512) cp16(smb + KB_W2 + i * 16, p + i * 16);
        CP_COMMIT();
    }
    if (tid < 256) b2s[tid] = b2[tid];

    const int nq = 2 * ntiles;

    // ---- prefetch first two quadrants ----
    {
        int q0 = blockIdx.x;
        if (q0 < nq) {
            const char* src = (const char*)(d_x1 + (size_t)(q0 >> 1) * 33792 + (q0 & 1) * 16896);
            for (int i = tid; i < 2112; i += 512) cp16(smb + KB_B0 + i * 16, src + i * 16);
        }
        CP_COMMIT();
        int q1 = blockIdx.x + 148;
        if (q1 < nq) {
            const char* src = (const char*)(d_x1 + (size_t)(q1 >> 1) * 33792 + (q1 & 1) * 16896);
            for (int i = tid; i < 2112; i += 512) cp16(smb + KB_B0 + KB_BSZ + i * 16, src + i * 16);
        }
        CP_COMMIT();
    }

    const uint32_t bBase = smb + KB_W2 + (uint32_t)(((Cb + bN) * 264 + bKoff) * 2);
    int buf = 0;

    for (int qid = blockIdx.x; qid < nq; qid += 148) {
        CP_WAITN(1);       // current buffer's x1 (and W2 on first iter) resident
        __syncthreads();

        const uint32_t bufb = smb + KB_B0 + buf * KB_BSZ;

        // gids for this quadrant's 64 rows
        if (tid < 64) {
            int grow = (qid >> 1) * 128 + (qid & 1) * 64 + tid;
            gids[tid] = (grow < n_atoms) ? graph_ids[grow] : -1;
        }

        // ---- GEMM: 64 x 256, K=256 ----
        float acc[32];
        #pragma unroll
        for (int i = 0; i < 32; i++) acc[i] = 0.f;
        const uint32_t aBase = bufb + (uint32_t)(((Rb + aRow) * 264 + aKoff) * 2);
        #pragma unroll
        for (int ks = 0; ks < 16; ks++) {
            uint32_t aH[8];
            ldsm4(aH[0], aH[1], aH[2], aH[3], aBase + ks * 32);
            ldsm4(aH[4], aH[5], aH[6], aH[7], aBase + 16 * 528 + ks * 32);
            #pragma unroll
            for (int nfp = 0; nfp < 2; nfp++) {
                uint32_t b0a, b1a, b0b, b1b;
                ldsm4(b0a, b1a, b0b, b1b, bBase + nfp * 16 * 528 + ks * 32);
                #pragma unroll
                for (int mf = 0; mf < 2; mf++) {
                    mma_f16(acc + (mf * 4 + nfp * 2) * 4,
                            aH[mf*4], aH[mf*4+1], aH[mf*4+2], aH[mf*4+3], b0a, b1a);
                    mma_f16(acc + (mf * 4 + nfp * 2 + 1) * 4,
                            aH[mf*4], aH[mf*4+1], aH[mf*4+2], aH[mf*4+3], b0b, b1b);
                }
            }
        }
        __syncthreads();   // all reads of buf done; X2 may alias it

        // ---- X2 = relu(acc + b2) as fp16 [64][264] into buf ----
        #pragma unroll
        for (int mf = 0; mf < 2; mf++) {
            #pragma unroll
            for (int nt = 0; nt < 4; nt++) {
                int idx = (mf * 4 + nt) * 4;
                int c = Cb + nt * 8 + m * 2;
                int R = Rb + mf * 16 + q;
                float v0 = fmaxf(acc[idx+0] + b2s[c],     0.f);
                float v1 = fmaxf(acc[idx+1] + b2s[c + 1], 0.f);
                float v2 = fmaxf(acc[idx+2] + b2s[c],     0.f);
                float v3 = fmaxf(acc[idx+3] + b2s[c + 1], 0.f);
                uint32_t off = (uint32_t)((R * 264 + c) * 2);
                sts32(bufb + off, pack2h(v0, v1));
                sts32(bufb + off + 4224, pack2h(v2, v3));   // row +8
            }
        }
        __syncthreads();

        // ---- segmented pool over sorted gids, then atomics ----
        {
            const int col = tid & 255;
            const int rlo = (tid >> 8) * 32;
            const __half* X2h = (const __half*)(sm + KB_B0 + buf * KB_BSZ);
            int cur = -1;
            float s = 0.f;
            #pragma unroll 8
            for (int rr = 0; rr < 32; rr++) {
                int r = rlo + rr;
                int g = gids[r];
                if (g != cur) {
                    if (cur >= 0) atomicAdd(&d_pooled[(size_t)cur * DH + col], s);
                    cur = g;
                    s = 0.f;
                }
                if (g >= 0) s += __half2float(X2h[r * 264 + col]);
            }
            if (cur >= 0) atomicAdd(&d_pooled[(size_t)cur * DH + col], s);
        }
        __syncthreads();   // pool reads done before buf refill

        // ---- prefetch quadrant qid+296 into this buffer ----
        {
            int qn = qid + 296;
            if (qn < nq) {
                const char* src = (const char*)(d_x1 + (size_t)(qn >> 1) * 33792 + (qn & 1) * 16896);
                for (int i = tid; i < 2112; i += 512) cp16(bufb + i * 16, src + i * 16);
            }
            CP_COMMIT();   // unconditional: keeps group accounting uniform
        }
        buf ^= 1;
    }
}

// ---------------------------------------------------------------------------
// Kernel 2: graph MLP, fp16 mma + ldmatrix, 64-graph tile (unchanged, ~25us)
// ---------------------------------------------------------------------------
#define GA     0
#define GW     33792
#define GWSTR  69632
#define GSO_BG1 173056
#define GSO_WS  174080
#define GSO_RS  175104
#define GRAPH_SMEM_BYTES 176128
#define TILE 64

extern "C" __global__ void __launch_bounds__(256, 1)
graph_kernel(const float* __restrict__ bg1, const float* __restrict__ Wg2,
             const float* __restrict__ bg2, float* __restrict__ out, int num_graphs)
{
    extern __shared__ unsigned char sm[];
    const uint32_t smb = smem_to_u32(sm);
    const int tid = threadIdx.x;
    const int l   = tid & 31;
    const int q   = l >> 2;
    const int m   = l & 3;
    const int w   = tid >> 5;
    const int wm  = w >> 2;
    const int wn  = w & 3;
    const int Rb  = wm * 32;
    const int Cb  = wn * 64;
    const int g0  = blockIdx.x * TILE;

    const int aRow  = l & 15;
    const int aKoff = (l >> 4) * 8;
    const int bN    = (l >> 4) * 8 + (l & 7);
    const int bKoff = ((l >> 3) & 1) * 8;

    float* bg1s = (float*)(sm + GSO_BG1);
    float* wsv  = (float*)(sm + GSO_WS);
    float* rs   = (float*)(sm + GSO_RS);

    #pragma unroll
    for (int cc = 0; cc < 2; cc++) {
        const char* p = (const char*)&d_Wg1h[cc][0];
        uint32_t dst = smb + GW + cc * GWSTR;
        #pragma unroll
        for (int it = 0; it < 17; it++) {
            int o = (tid + it * 256) * 16;
            cp16(dst + o, p + o);
        }
        CP_COMMIT();
    }

    bg1s[tid] = bg1[tid];
    wsv[tid]  = Wg2[tid];

    #pragma unroll 4
    for (int it = 0; it < 16; it++) {
        int idx = tid + it * 256;
        int r = idx >> 6, c = (idx & 63) * 4;
        float4 v = make_float4(0.f, 0.f, 0.f, 0.f);
        if (g0 + r < num_graphs)
            v = *(const float4*)(d_pooled + (size_t)(g0 + r) * DH + c);
        uint32_t off = (uint32_t)(r * 264 + c) * 2;
        *(uint2*)(sm + GA + off) = make_uint2(pack2h(v.x, v.y), pack2h(v.z, v.w));
    }

    float acc[64];
    #pragma unroll
    for (int i = 0; i < 64; i++) acc[i] = 0.f;

    {
        const uint32_t aBase = smb + GA + (uint32_t)(((Rb + aRow) * 264 + aKoff) * 2);
        #pragma unroll
        for (int half = 0; half < 2; half++) {
            if (half == 0) CP_WAITN(1); else CP_WAITN(0);
            __syncthreads();
            const uint32_t bBase = smb + GW + half * GWSTR
                                 + (uint32_t)(((Cb + bN) * 136 + bKoff) * 2);
            #pragma unroll
            for (int kk = 0; kk < 8; kk++) {
                uint32_t aH[8];
                ldsm4(aH[0], aH[1], aH[2], aH[3], aBase + half * 256 + kk * 32);
                ldsm4(aH[4], aH[5], aH[6], aH[7], aBase + 16 * 528 + half * 256 + kk * 32);
                #pragma unroll
                for (int nfp = 0; nfp < 4; nfp++) {
                    uint32_t b0a, b1a, b0b, b1b;
                    ldsm4(b0a, b1a, b0b, b1b, bBase + nfp * 16 * 272 + kk * 32);
                    #pragma unroll
                    for (int mf = 0; mf < 2; mf++) {
                        mma_f16(acc + (mf * 8 + nfp * 2) * 4,
                                aH[mf*4], aH[mf*4+1], aH[mf*4+2], aH[mf*4+3], b0a, b1a);
                        mma_f16(acc + (mf * 8 + nfp * 2 + 1) * 4,
                                aH[mf*4], aH[mf*4+1], aH[mf*4+2], aH[mf*4+3], b0b, b1b);
                    }
                }
            }
        }
    }

    #pragma unroll
    for (int mf = 0; mf < 2; mf++) {
        float p0 = 0.f, p1 = 0.f;
        #pragma unroll
        for (int nf = 0; nf < 8; nf++) {
            int idx = (mf * 8 + nf) * 4;
            int c = Cb + nf * 8 + m * 2;
            float w0 = wsv[c], w1 = wsv[c + 1];
            p0 += fmaxf(acc[idx+0] + bg1s[c],     0.f) * w0
                + fmaxf(acc[idx+1] + bg1s[c + 1], 0.f) * w1;
            p1 += fmaxf(acc[idx+2] + bg1s[c],     0.f) * w0
                + fmaxf(acc[idx+3] + bg1s[c + 1], 0.f) * w1;
        }
        p0 += __shfl_xor_sync(0xffffffffu, p0, 1);
        p0 += __shfl_xor_sync(0xffffffffu, p0, 2);
        p1 += __shfl_xor_sync(0xffffffffu, p1, 1);
        p1 += __shfl_xor_sync(0xffffffffu, p1, 2);
        if (m == 0) {
            int R = Rb + mf * 16 + q;
            rs[R * 4 + wn]       = p0;
            rs[(R + 8) * 4 + wn] = p1;
        }
    }
    __syncthreads();
    if (tid < TILE) {
        int g = g0 + tid;
        if (g < num_graphs)
            out[g] = rs[tid * 4] + rs[tid * 4 + 1] + rs[tid * 4 + 2] + rs[tid * 4 + 3] + bg2[0];
    }
}

// ---------------------------------------------------------------------------
extern "C" void kernel_launch(void* const* d_in, const int* in_sizes, int n_in,
                              void* d_out, int out_size) {
    const float* h         = (const float*)d_in[0];
    const int*   graph_ids = (const int*)  d_in[1];
    const int base = (n_in >= 11) ? 3 : 2;   // skip num_graphs scalar slot if present
    const float* W1  = (const float*)d_in[base + 0];
    const float* b1  = (const float*)d_in[base + 1];
    const float* W2  = (const float*)d_in[base + 2];
    const float* b2  = (const float*)d_in[base + 3];
    const float* Wg1 = (const float*)d_in[base + 4];
    const float* bg1 = (const float*)d_in[base + 5];
    const float* Wg2 = (const float*)d_in[base + 6];
    const float* bg2 = (const float*)d_in[base + 7];
    float* out = (float*)d_out;

    const int n_atoms = in_sizes[0] / DIN;
    int ntiles = (n_atoms + 127) / 128;
    if (ntiles > NTILES_MAX) ntiles = NTILES_MAX;
    const int G = out_size;                  // D_OUT = 1

    static bool attrs_set = false;
    if (!attrs_set) {
        cudaFuncSetAttribute(layer1_kernel,
                             cudaFuncAttributeMaxDynamicSharedMemorySize, KA_SMEM);
        cudaFuncSetAttribute(layer2_kernel,
                             cudaFuncAttributeMaxDynamicSharedMemorySize, KB_SMEM);
        cudaFuncSetAttribute(graph_kernel,
                             cudaFuncAttributeMaxDynamicSharedMemorySize, GRAPH_SMEM_BYTES);
        attrs_set = true;
    }

    prep_kernel<<<(DIN * DH + 2 * DH * DH + 255) / 256, 256>>>(W1, W2, Wg1);
    zero_pooled_kernel<<<512, 256>>>(G * DH);

    layer1_kernel<<<148, 512, KA_SMEM>>>(h, b1, n_atoms, ntiles);
    layer2_kernel<<<148, 512, KB_SMEM>>>(graph_ids, b2, n_atoms, ntiles);

    int gblocks = (G + TILE - 1) / TILE;
    graph_kernel<<<gblocks, 256, GRAPH_SMEM_BYTES>>>(bg1, Wg2, bg2, out, G);
}